// round 13
// baseline (speedup 1.0000x reference)
#include <cuda_runtime.h>
#include <cuda_fp16.h>
#include <cstdint>

// Problem constants
#define NIMG 256          // B*L
#define CCH  64
#define HW   32
#define IMGSZ (CCH*HW*HW) // 65536 floats per image
#define NODES 256

// Paired-fp16 tensors: [n][g4][cp8][1024] half2(u32), half2 = (ci=g*16+2cp, +1)
#define H2_PER_IMG 32768
__device__ uint32_t g_xh[NIMG * H2_PER_IMG];   // pairified fp16 x
__device__ uint32_t g_xs[NIMG * H2_PER_IMG];   // aggregated x (fp16)
__device__ uint32_t g_h [NIMG * H2_PER_IMG];   // hidden (fp16)
__device__ uint32_t g_hs[NIMG * H2_PER_IMG];   // aggregated hidden (fp16)
__device__ int g_nbr[NODES * 8];
__device__ int g_cnt[NODES];

// Weights fp16: [layer2][chunk8][tap9][qid8][q4][nt pad10] uint2
#define WC_U2    2880                  // uint2 per chunk: 9*8*4*10
#define W_TAP_U4 160                   // uint4 per tap
#define WPREP_TOTAL (2*8*WC_U2)        // 46080 uint2
__device__ uint2 g_wprep[WPREP_TOTAL];

// patch (half2/u32 elems): [cp8][row10][36], interior at col 2+gx (8B-aligned)
#define P_CSTR 360
#define P_RSTR 36
#define P_ELEMS 2880                   // u32 per buffer
#define SMEM_BYTES (2*P_ELEMS*4 + 2*WC_U2*8)   // 69120

#define PREP_BLOCKS 180                // 180*256 == WPREP_TOTAL exactly
#define CVT_E4 (NIMG * H2_PER_IMG / 4) // 2097152 uint4 elems
#define CVT_BLOCKS (CVT_E4 / 256)      // 8192

#define CONV_THREADS 512               // 16 warps: wid = row(0-7) | coh(0-1)<<3

__device__ __forceinline__ uint32_t pack_h2(float a, float b) {
    __half2 h = __floats2half2_rn(a, b);
    return *(uint32_t*)&h;
}
__device__ __forceinline__ float2 h2f(uint32_t u) {
    __half2 h = *(__half2*)&u;
    return __half22float2(h);
}
__device__ __forceinline__ void cp16(void* s, const void* g) {
    uint32_t sa = (uint32_t)__cvta_generic_to_shared(s);
    asm volatile("cp.async.cg.shared.global [%0], [%1], 16;" :: "r"(sa), "l"(g));
}
__device__ __forceinline__ void cp8(void* s, const void* g) {
    uint32_t sa = (uint32_t)__cvta_generic_to_shared(s);
    asm volatile("cp.async.ca.shared.global [%0], [%1], 8;" :: "r"(sa), "l"(g));
}
__device__ __forceinline__ void mma_f16(float& d0, float& d1, float& d2, float& d3,
                                        uint32_t a0, uint32_t a1, uint32_t a2, uint32_t a3,
                                        uint32_t b0, uint32_t b1) {
    asm volatile(
        "mma.sync.aligned.m16n8k16.row.col.f32.f16.f16.f32 "
        "{%0,%1,%2,%3},{%4,%5,%6,%7},{%8,%9},{%0,%1,%2,%3};"
        : "+f"(d0), "+f"(d1), "+f"(d2), "+f"(d3)
        : "r"(a0), "r"(a1), "r"(a2), "r"(a3), "r"(b0), "r"(b1));
}

// ---------------------------------------------------------------------------
// Mask setup: detect dtype then build neighbor lists, one single-block kernel
// ---------------------------------------------------------------------------
__global__ void mask_setup_kernel(const void* m) {
    __shared__ int bad;
    __shared__ int smode;
    int row = threadIdx.x;
    if (row == 0) bad = 0;
    __syncthreads();
    {
        const unsigned char* p = (const unsigned char*)m + row * 64;
        int c = 0;
        for (int j = 0; j < 64; j++) c += (p[j] != 0);
        if (c != 4) atomicOr(&bad, 1);
    }
    __syncthreads();
    int ok8 = !bad;
    __syncthreads();
    if (row == 0) bad = 0;
    __syncthreads();
    if (!ok8) {
        const unsigned short* p = (const unsigned short*)m + row * 64;
        int c = 0;
        for (int j = 0; j < 64; j++) c += (p[j] != 0);
        if (c != 4) atomicOr(&bad, 1);
    }
    __syncthreads();
    if (row == 0) smode = ok8 ? 0 : ((!bad) ? 1 : 2);
    __syncthreads();

    int mode = smode;
    int base = (row >> 6) << 6;
    int cnt = 0;
    if (mode == 0) {
        const unsigned char* p = (const unsigned char*)m + row * 64;
        for (int j = 0; j < 64; j++)
            if (p[j]) { if (cnt < 8) g_nbr[row * 8 + cnt] = base + j; cnt++; }
    } else if (mode == 1) {
        const unsigned short* p = (const unsigned short*)m + row * 64;
        for (int j = 0; j < 64; j++)
            if (p[j]) { if (cnt < 8) g_nbr[row * 8 + cnt] = base + j; cnt++; }
    } else {
        const unsigned int* p = (const unsigned int*)m + row * 64;
        for (int j = 0; j < 64; j++)
            if (p[j]) { if (cnt < 8) g_nbr[row * 8 + cnt] = base + j; cnt++; }
    }
    g_cnt[row] = cnt;
}

// ---------------------------------------------------------------------------
// Fused: weight prep (blocks 0..179) + vectorized x->fp16 convert (rest)
// ---------------------------------------------------------------------------
__global__ void prep_cvt_kernel(const float* __restrict__ w_x0, const float* __restrict__ w_n0,
                                const float* __restrict__ w_x1, const float* __restrict__ w_n1,
                                const float* __restrict__ x, uint4* __restrict__ xh4) {
    if (blockIdx.x < PREP_BLOCKS) {
        int e = blockIdx.x * 256 + threadIdx.x;
        int nt = e % 10; int t = e / 10;
        int q   = t & 3;  t >>= 2;
        int qid = t & 7;  t >>= 3;
        int tap = t % 9;  t /= 9;
        int chunk = t & 7;
        int layer = t >> 3;
        int half = chunk >> 2;
        int cb = (chunk & 3) * 16;
        const float* w = layer ? (half ? w_n1 : w_x1) : (half ? w_n0 : w_x0);
        uint2 v = make_uint2(0u, 0u);
        if (nt < 8) {
            int co = nt * 8 + qid;
            const float* wc = w + co * 576 + tap;
            v.x = pack_h2(wc[(cb + 2 * q) * 9],     wc[(cb + 2 * q + 1) * 9]);
            v.y = pack_h2(wc[(cb + 2 * q + 8) * 9], wc[(cb + 2 * q + 9) * 9]);
        }
        g_wprep[e] = v;
    } else {
        int e4 = (blockIdx.x - PREP_BLOCKS) * 256 + threadIdx.x;
        int p4 = e4 & 255;
        int cp = (e4 >> 8) & 7;
        int g  = (e4 >> 11) & 3;
        int n  = e4 >> 13;
        int ci = g * 16 + cp * 2;
        const float* s = x + (size_t)(n * CCH + ci) * 1024 + p4 * 4;
        float4 lo = *(const float4*)s;
        float4 hi = *(const float4*)(s + 1024);
        xh4[e4] = make_uint4(pack_h2(lo.x, hi.x), pack_h2(lo.y, hi.y),
                             pack_h2(lo.z, hi.z), pack_h2(lo.w, hi.w));
    }
}

// ---------------------------------------------------------------------------
// Neighbor aggregation on fp16 (fp32 accumulate, fp16 out)
// ---------------------------------------------------------------------------
__global__ void agg_kernel(const uint4* __restrict__ src, uint4* __restrict__ dst) {
    int node = blockIdx.x;
    int cnt = g_cnt[node];
    if (cnt > 8) cnt = 8;
    int i0 = blockIdx.y * blockDim.x + threadIdx.x;
    int stride = gridDim.y * blockDim.x;
    int nb[8];
    for (int k = 0; k < cnt; k++) nb[k] = g_nbr[node * 8 + k];
    const int n4 = H2_PER_IMG / 4;
    for (int i = i0; i < n4; i += stride) {
        float2 a0 = make_float2(0.f, 0.f), a1 = a0, a2 = a0, a3 = a0;
        for (int k = 0; k < cnt; k++) {
            uint4 v = src[nb[k] * n4 + i];
            float2 t;
            t = h2f(v.x); a0.x += t.x; a0.y += t.y;
            t = h2f(v.y); a1.x += t.x; a1.y += t.y;
            t = h2f(v.z); a2.x += t.x; a2.y += t.y;
            t = h2f(v.w); a3.x += t.x; a3.y += t.y;
        }
        dst[node * n4 + i] = make_uint4(pack_h2(a0.x, a0.y), pack_h2(a1.x, a1.y),
                                        pack_h2(a2.x, a2.y), pack_h2(a3.x, a3.y));
    }
}

// ---------------------------------------------------------------------------
// Conv: fp16 m16n8k16, warp = 32px x 32co (co-split), 512-thread CTA,
// 8 K16 chunks, 2-stage cp.async pipeline
// ---------------------------------------------------------------------------
__device__ __forceinline__ void issue_chunk(uint32_t* pat, uint4* wdst,
                                            const uint4* __restrict__ wsrc,
                                            const uint32_t* __restrict__ img,
                                            int y0, int tid) {
    // weights: 1440 uint4
#pragma unroll
    for (int k = 0; k < 3; k++) {
        int idx = tid + k * CONV_THREADS;
        if (idx < WC_U2 / 2) cp16(wdst + idx, wsrc + idx);
    }
    // patch: 1280 cp8 ops (8 cp x 10 rows x 16 col-pairs)
#pragma unroll
    for (int k = 0; k < 3; k++) {
        int i = tid + k * CONV_THREADS;
        if (i < 1280) {
            int col = (i & 15) * 2;
            int r = (i >> 4) % 10;
            int cp = i / 160;
            int gy = y0 + r - 1;
            if (gy >= 0 && gy < HW)
                cp8(pat + cp * P_CSTR + r * P_RSTR + 2 + col,
                    img + cp * 1024 + gy * 32 + col);
        }
    }
    asm volatile("cp.async.commit_group;" ::: "memory");
}

__device__ __forceinline__ void compute_chunk(const uint32_t* __restrict__ pat,
                                              const uint4* __restrict__ wq,
                                              int w, int qid, int q, int wtbase,
                                              float (&acc)[2][4][4]) {
    uint4 bb[2][2];
#pragma unroll
    for (int j = 0; j < 2; j++) bb[0][j] = wq[wtbase + j];

#pragma unroll
    for (int tap = 0; tap < 9; tap++) {
        const int ty = tap / 3, tx = tap % 3;
        const int cur = tap & 1;
        if (tap < 8) {
            const uint4* wn = wq + (tap + 1) * W_TAP_U4 + wtbase;
#pragma unroll
            for (int j = 0; j < 2; j++) bb[1 - cur][j] = wn[j];
        }
        const int ro = (w + ty) * P_RSTR + qid + tx + 1;
        const int blo = q * P_CSTR + ro;
        const int bhi = (q + 4) * P_CSTR + ro;
        uint32_t a[2][4];
#pragma unroll
        for (int mt = 0; mt < 2; mt++) {
            const int xo = mt * 16;
            a[mt][0] = pat[blo + xo];
            a[mt][1] = pat[blo + xo + 8];
            a[mt][2] = pat[bhi + xo];
            a[mt][3] = pat[bhi + xo + 8];
        }
        const uint32_t* b = (const uint32_t*)bb[cur];
#pragma unroll
        for (int mt = 0; mt < 2; mt++)
#pragma unroll
            for (int nt = 0; nt < 4; nt++)
                mma_f16(acc[mt][nt][0], acc[mt][nt][1],
                        acc[mt][nt][2], acc[mt][nt][3],
                        a[mt][0], a[mt][1], a[mt][2], a[mt][3],
                        b[2 * nt], b[2 * nt + 1]);
    }
}

// EPI 0: fp32 out + residual; EPI 1: paired-fp16 out (h)
template <int EPI>
__global__ __launch_bounds__(CONV_THREADS, 1)
void conv_kernel(const uint32_t* __restrict__ inA, const uint32_t* __restrict__ inB,
                 const uint2* __restrict__ wlayer,
                 const float* __restrict__ bA, const float* __restrict__ bB,
                 const float* __restrict__ resid, void* __restrict__ outv) {
    extern __shared__ uint8_t smem[];
    uint32_t* patB[2];
    patB[0] = (uint32_t*)smem;
    patB[1] = patB[0] + P_ELEMS;
    uint4* wsmB[2];
    wsmB[0] = (uint4*)(patB[1] + P_ELEMS);
    wsmB[1] = wsmB[0] + WC_U2 / 2;

    const int n = blockIdx.y;
    const int rb = blockIdx.x;
    const int tid = threadIdx.x;
    const int wid = tid >> 5;
    const int w = wid & 7;           // image row within tile
    const int coh = wid >> 3;        // co half: 0 -> co 0..31, 1 -> co 32..63
    const int lane = tid & 31;
    const int qid = lane >> 2;
    const int q = lane & 3;
    const int y0 = rb * 8;

#pragma unroll
    for (int k = 0; k < 12; k++) {
        int i = tid + k * CONV_THREADS;
        if (i < 2 * P_ELEMS) patB[0][i] = 0u;
    }
    __syncthreads();

    float acc[2][4][4];
#pragma unroll
    for (int mt = 0; mt < 2; mt++)
#pragma unroll
        for (int nt = 0; nt < 4; nt++)
#pragma unroll
            for (int r = 0; r < 4; r++) acc[mt][nt][r] = 0.f;

    issue_chunk(patB[0], wsmB[0], (const uint4*)wlayer, inA + n * H2_PER_IMG, y0, tid);
    asm volatile("cp.async.wait_group 0;" ::: "memory");
    __syncthreads();

    // each warp reads only its co-half: 2 uint4 per tap (subset of proven pattern)
    const int wtbase = (qid * 4 + q) * 5 + coh * 2;

    for (int it = 0; it < 8; ++it) {
        const int p = it & 1;
        if (it < 7) {
            const int jt = it + 1;
            const uint32_t* img = ((jt >= 4) ? inB : inA) + (n * 4 + (jt & 3)) * 8192;
            issue_chunk(patB[1 - p], wsmB[1 - p], (const uint4*)(wlayer + jt * WC_U2),
                        img, y0, tid);
        }
        compute_chunk(patB[p], wsmB[p], w, qid, q, wtbase, acc);
        asm volatile("cp.async.wait_group 0;" ::: "memory");
        __syncthreads();
    }

    const int gy = y0 + w;
    const float cntf = (float)g_cnt[n];
#pragma unroll
    for (int nt = 0; nt < 4; nt++) {
        const int co = coh * 32 + nt * 8 + 2 * q;
        const float bias0 = bA[co]     + cntf * bB[co];
        const float bias1 = bA[co + 1] + cntf * bB[co + 1];
#pragma unroll
        for (int mt = 0; mt < 2; mt++) {
            const int xa = mt * 16 + qid;
            const int xc = xa + 8;
            float r0 = acc[mt][nt][0] + bias0;   // (xa, co)
            float r1 = acc[mt][nt][1] + bias1;   // (xa, co+1)
            float r2 = acc[mt][nt][2] + bias0;   // (xc, co)
            float r3 = acc[mt][nt][3] + bias1;   // (xc, co+1)
            if (EPI == 0) {
                float* out = (float*)outv;
                const int o0 = ((n * CCH + co) * HW + gy) * HW;
                r0 += resid[o0 + xa];
                r1 += resid[o0 + 1024 + xa];
                r2 += resid[o0 + xc];
                r3 += resid[o0 + 1024 + xc];
                out[o0 + xa]        = fmaxf(r0, 0.f);
                out[o0 + 1024 + xa] = fmaxf(r1, 0.f);
                out[o0 + xc]        = fmaxf(r2, 0.f);
                out[o0 + 1024 + xc] = fmaxf(r3, 0.f);
            } else {
                uint32_t* out = (uint32_t*)outv;
                const int b0 = ((n * 4 + (co >> 4)) * 8 + ((co >> 1) & 7)) * 1024 + gy * 32;
                out[b0 + xa] = pack_h2(fmaxf(r0, 0.f), fmaxf(r1, 0.f));
                out[b0 + xc] = pack_h2(fmaxf(r2, 0.f), fmaxf(r3, 0.f));
            }
        }
    }
}

// ---------------------------------------------------------------------------
extern "C" void kernel_launch(void* const* d_in, const int* in_sizes, int n_in,
                              void* d_out, int out_size) {
    const float* x    = (const float*)d_in[0];
    const float* w_x0 = (const float*)d_in[1];
    const float* b_x0 = (const float*)d_in[2];
    const float* w_n0 = (const float*)d_in[3];
    const float* b_n0 = (const float*)d_in[4];
    const float* w_x1 = (const float*)d_in[5];
    const float* b_x1 = (const float*)d_in[6];
    const float* w_n1 = (const float*)d_in[7];
    const float* b_n1 = (const float*)d_in[8];
    const void*  msk  = d_in[9];
    float* out = (float*)d_out;

    uint32_t *xh, *xs, *h, *hs;
    uint2* wprep;
    cudaGetSymbolAddress((void**)&xh, g_xh);
    cudaGetSymbolAddress((void**)&xs, g_xs);
    cudaGetSymbolAddress((void**)&h,  g_h);
    cudaGetSymbolAddress((void**)&hs, g_hs);
    cudaGetSymbolAddress((void**)&wprep, g_wprep);

    static bool attr_set = false;
    if (!attr_set) {
        cudaFuncSetAttribute(conv_kernel<0>, cudaFuncAttributeMaxDynamicSharedMemorySize,
                             SMEM_BYTES);
        cudaFuncSetAttribute(conv_kernel<1>, cudaFuncAttributeMaxDynamicSharedMemorySize,
                             SMEM_BYTES);
        attr_set = true;
    }

    dim3 agrid(NODES, 16);
    dim3 cgrid(4, NIMG);

    // launch 0: mask setup
    mask_setup_kernel<<<1, 256>>>(msk);
    // launch 1: weight prep + x->fp16 convert
    prep_cvt_kernel<<<PREP_BLOCKS + CVT_BLOCKS, 256>>>(w_x0, w_n0, w_x1, w_n1,
                                                       x, (uint4*)xh);
    // launch 2: agg1;  launch 3: conv1 (ncu sample slot)
    agg_kernel<<<agrid, 256>>>((const uint4*)xh, (uint4*)xs);
    conv_kernel<1><<<cgrid, CONV_THREADS, SMEM_BYTES>>>(xh, xs, wprep, b_x0, b_n0,
                                                        nullptr, (void*)h);
    // launch 4: agg2;  launch 5: conv2
    agg_kernel<<<agrid, 256>>>((const uint4*)h, (uint4*)hs);
    conv_kernel<0><<<cgrid, CONV_THREADS, SMEM_BYTES>>>(h, hs, wprep + 8 * WC_U2,
                                                        b_x1, b_n1, x, (void*)out);
}

// round 14
// speedup vs baseline: 1.1374x; 1.1374x over previous
#include <cuda_runtime.h>
#include <cuda_fp16.h>
#include <cstdint>

// Problem constants
#define NIMG 256          // B*L
#define CCH  64
#define HW   32
#define IMGSZ (CCH*HW*HW) // 65536 floats per image
#define NODES 256

// Paired-fp16 tensors: [n][g4][cp8][1024] half2(u32), half2 = (ci=g*16+2cp, +1)
#define H2_PER_IMG 32768
__device__ uint32_t g_xh[NIMG * H2_PER_IMG];   // pairified fp16 x
__device__ uint32_t g_xs[NIMG * H2_PER_IMG];   // aggregated x (fp16)
__device__ uint32_t g_h [NIMG * H2_PER_IMG];   // hidden (fp16)
__device__ uint32_t g_hs[NIMG * H2_PER_IMG];   // aggregated hidden (fp16)
__device__ int g_nbr[NODES * 8];
__device__ int g_cnt[NODES];

// Weights fp16: [layer2][chunk8][tap9][qid8][q4][nt pad10] uint2
#define WC_U2    2880                  // uint2 per chunk: 9*8*4*10
#define W_TAP_U4 160                   // uint4 per tap
#define WPREP_TOTAL (2*8*WC_U2)        // 46080 uint2
__device__ uint2 g_wprep[WPREP_TOTAL];

// patch (half2/u32 elems): [cp8][row10][36], interior at col 2+gx (8B-aligned)
#define P_CSTR 360
#define P_RSTR 36
#define P_ELEMS 2880                   // u32 per buffer
#define SMEM_BYTES (2*P_ELEMS*4 + 2*WC_U2*8)   // 69120

#define PREP_BLOCKS 180                // 180*256 == WPREP_TOTAL exactly
#define CVT_E4 (NIMG * H2_PER_IMG / 4) // 2097152 uint4 elems
#define CVT_BLOCKS (CVT_E4 / 256)      // 8192

__device__ __forceinline__ uint32_t pack_h2(float a, float b) {
    __half2 h = __floats2half2_rn(a, b);
    return *(uint32_t*)&h;
}
__device__ __forceinline__ float2 h2f(uint32_t u) {
    __half2 h = *(__half2*)&u;
    return __half22float2(h);
}
__device__ __forceinline__ void cp16(void* s, const void* g) {
    uint32_t sa = (uint32_t)__cvta_generic_to_shared(s);
    asm volatile("cp.async.cg.shared.global [%0], [%1], 16;" :: "r"(sa), "l"(g));
}
__device__ __forceinline__ void cp8(void* s, const void* g) {
    uint32_t sa = (uint32_t)__cvta_generic_to_shared(s);
    asm volatile("cp.async.ca.shared.global [%0], [%1], 8;" :: "r"(sa), "l"(g));
}
__device__ __forceinline__ void mma_f16(float& d0, float& d1, float& d2, float& d3,
                                        uint32_t a0, uint32_t a1, uint32_t a2, uint32_t a3,
                                        uint32_t b0, uint32_t b1) {
    asm volatile(
        "mma.sync.aligned.m16n8k16.row.col.f32.f16.f16.f32 "
        "{%0,%1,%2,%3},{%4,%5,%6,%7},{%8,%9},{%0,%1,%2,%3};"
        : "+f"(d0), "+f"(d1), "+f"(d2), "+f"(d3)
        : "r"(a0), "r"(a1), "r"(a2), "r"(a3), "r"(b0), "r"(b1));
}

// ---------------------------------------------------------------------------
// Mask setup: detect dtype then build neighbor lists, one single-block kernel
// ---------------------------------------------------------------------------
__global__ void mask_setup_kernel(const void* m) {
    __shared__ int bad;
    __shared__ int smode;
    int row = threadIdx.x;
    if (row == 0) bad = 0;
    __syncthreads();
    {
        const unsigned char* p = (const unsigned char*)m + row * 64;
        int c = 0;
        for (int j = 0; j < 64; j++) c += (p[j] != 0);
        if (c != 4) atomicOr(&bad, 1);
    }
    __syncthreads();
    int ok8 = !bad;
    __syncthreads();
    if (row == 0) bad = 0;
    __syncthreads();
    if (!ok8) {
        const unsigned short* p = (const unsigned short*)m + row * 64;
        int c = 0;
        for (int j = 0; j < 64; j++) c += (p[j] != 0);
        if (c != 4) atomicOr(&bad, 1);
    }
    __syncthreads();
    if (row == 0) smode = ok8 ? 0 : ((!bad) ? 1 : 2);
    __syncthreads();

    int mode = smode;
    int base = (row >> 6) << 6;
    int cnt = 0;
    if (mode == 0) {
        const unsigned char* p = (const unsigned char*)m + row * 64;
        for (int j = 0; j < 64; j++)
            if (p[j]) { if (cnt < 8) g_nbr[row * 8 + cnt] = base + j; cnt++; }
    } else if (mode == 1) {
        const unsigned short* p = (const unsigned short*)m + row * 64;
        for (int j = 0; j < 64; j++)
            if (p[j]) { if (cnt < 8) g_nbr[row * 8 + cnt] = base + j; cnt++; }
    } else {
        const unsigned int* p = (const unsigned int*)m + row * 64;
        for (int j = 0; j < 64; j++)
            if (p[j]) { if (cnt < 8) g_nbr[row * 8 + cnt] = base + j; cnt++; }
    }
    g_cnt[row] = cnt;
}

// ---------------------------------------------------------------------------
// Fused: weight prep (blocks 0..179) + vectorized x->fp16 convert (rest)
// ---------------------------------------------------------------------------
__global__ void prep_cvt_kernel(const float* __restrict__ w_x0, const float* __restrict__ w_n0,
                                const float* __restrict__ w_x1, const float* __restrict__ w_n1,
                                const float* __restrict__ x, uint4* __restrict__ xh4) {
    if (blockIdx.x < PREP_BLOCKS) {
        int e = blockIdx.x * 256 + threadIdx.x;
        int nt = e % 10; int t = e / 10;
        int q   = t & 3;  t >>= 2;
        int qid = t & 7;  t >>= 3;
        int tap = t % 9;  t /= 9;
        int chunk = t & 7;
        int layer = t >> 3;
        int half = chunk >> 2;
        int cb = (chunk & 3) * 16;
        const float* w = layer ? (half ? w_n1 : w_x1) : (half ? w_n0 : w_x0);
        uint2 v = make_uint2(0u, 0u);
        if (nt < 8) {
            int co = nt * 8 + qid;
            const float* wc = w + co * 576 + tap;
            v.x = pack_h2(wc[(cb + 2 * q) * 9],     wc[(cb + 2 * q + 1) * 9]);
            v.y = pack_h2(wc[(cb + 2 * q + 8) * 9], wc[(cb + 2 * q + 9) * 9]);
        }
        g_wprep[e] = v;
    } else {
        int e4 = (blockIdx.x - PREP_BLOCKS) * 256 + threadIdx.x;
        int p4 = e4 & 255;
        int cp = (e4 >> 8) & 7;
        int g  = (e4 >> 11) & 3;
        int n  = e4 >> 13;
        int ci = g * 16 + cp * 2;
        const float* s = x + (size_t)(n * CCH + ci) * 1024 + p4 * 4;
        float4 lo = *(const float4*)s;
        float4 hi = *(const float4*)(s + 1024);
        xh4[e4] = make_uint4(pack_h2(lo.x, hi.x), pack_h2(lo.y, hi.y),
                             pack_h2(lo.z, hi.z), pack_h2(lo.w, hi.w));
    }
}

// ---------------------------------------------------------------------------
// Neighbor aggregation on fp16 (fp32 accumulate, fp16 out)
// ---------------------------------------------------------------------------
__global__ void agg_kernel(const uint4* __restrict__ src, uint4* __restrict__ dst) {
    int node = blockIdx.x;
    int cnt = g_cnt[node];
    if (cnt > 8) cnt = 8;
    int i0 = blockIdx.y * blockDim.x + threadIdx.x;
    int stride = gridDim.y * blockDim.x;
    int nb[8];
    for (int k = 0; k < cnt; k++) nb[k] = g_nbr[node * 8 + k];
    const int n4 = H2_PER_IMG / 4;
    for (int i = i0; i < n4; i += stride) {
        float2 a0 = make_float2(0.f, 0.f), a1 = a0, a2 = a0, a3 = a0;
        for (int k = 0; k < cnt; k++) {
            uint4 v = src[nb[k] * n4 + i];
            float2 t;
            t = h2f(v.x); a0.x += t.x; a0.y += t.y;
            t = h2f(v.y); a1.x += t.x; a1.y += t.y;
            t = h2f(v.z); a2.x += t.x; a2.y += t.y;
            t = h2f(v.w); a3.x += t.x; a3.y += t.y;
        }
        dst[node * n4 + i] = make_uint4(pack_h2(a0.x, a0.y), pack_h2(a1.x, a1.y),
                                        pack_h2(a2.x, a2.y), pack_h2(a3.x, a3.y));
    }
}

// ---------------------------------------------------------------------------
// Conv: fp16 m16n8k16, R12 tile (warp = 32px x 64co, 256 thr, 2 CTA/SM),
// 8 K16 chunks, 2-stage cp.async pipeline, A+B register double-buffering
// ---------------------------------------------------------------------------
__device__ __forceinline__ void issue_chunk(uint32_t* pat, uint4* wdst,
                                            const uint4* __restrict__ wsrc,
                                            const uint32_t* __restrict__ img,
                                            int y0, int tid) {
#pragma unroll
    for (int k = 0; k < 6; k++) {
        int idx = tid + k * 256;
        if (idx < WC_U2 / 2) cp16(wdst + idx, wsrc + idx);
    }
#pragma unroll
    for (int k = 0; k < 5; k++) {
        int i = tid + k * 256;
        int col = (i & 15) * 2;
        int r = (i >> 4) % 10;
        int cp = i / 160;
        int gy = y0 + r - 1;
        if (gy >= 0 && gy < HW)
            cp8(pat + cp * P_CSTR + r * P_RSTR + 2 + col,
                img + cp * 1024 + gy * 32 + col);
    }
    asm volatile("cp.async.commit_group;" ::: "memory");
}

__device__ __forceinline__ void load_a(const uint32_t* __restrict__ pat,
                                       int w, int qid, int q, int tap,
                                       uint32_t (&a)[8]) {
    const int ty = tap / 3, tx = tap % 3;
    const int ro = (w + ty) * P_RSTR + qid + tx + 1;
    const int blo = q * P_CSTR + ro;
    const int bhi = (q + 4) * P_CSTR + ro;
#pragma unroll
    for (int mt = 0; mt < 2; mt++) {
        const int xo = mt * 16;
        a[mt * 4 + 0] = pat[blo + xo];
        a[mt * 4 + 1] = pat[blo + xo + 8];
        a[mt * 4 + 2] = pat[bhi + xo];
        a[mt * 4 + 3] = pat[bhi + xo + 8];
    }
}

__device__ __forceinline__ void compute_chunk(const uint32_t* __restrict__ pat,
                                              const uint4* __restrict__ wq,
                                              int w, int qid, int q, int wtbase,
                                              float (&acc)[2][8][4]) {
    uint4 bb[2][4];
    uint32_t aa[2][8];
#pragma unroll
    for (int j = 0; j < 4; j++) bb[0][j] = wq[wtbase + j];
    load_a(pat, w, qid, q, 0, aa[0]);

#pragma unroll
    for (int tap = 0; tap < 9; tap++) {
        const int cur = tap & 1;
        if (tap < 8) {
            const uint4* wn = wq + (tap + 1) * W_TAP_U4 + wtbase;
#pragma unroll
            for (int j = 0; j < 4; j++) bb[1 - cur][j] = wn[j];
            load_a(pat, w, qid, q, tap + 1, aa[1 - cur]);
        }
        const uint32_t* a = aa[cur];
        const uint32_t* b = (const uint32_t*)bb[cur];
#pragma unroll
        for (int mt = 0; mt < 2; mt++)
#pragma unroll
            for (int nt = 0; nt < 8; nt++)
                mma_f16(acc[mt][nt][0], acc[mt][nt][1],
                        acc[mt][nt][2], acc[mt][nt][3],
                        a[mt * 4 + 0], a[mt * 4 + 1], a[mt * 4 + 2], a[mt * 4 + 3],
                        b[2 * nt], b[2 * nt + 1]);
    }
}

// EPI 0: fp32 out + residual; EPI 1: paired-fp16 out (h)
template <int EPI>
__global__ __launch_bounds__(256, 2)
void conv_kernel(const uint32_t* __restrict__ inA, const uint32_t* __restrict__ inB,
                 const uint2* __restrict__ wlayer,
                 const float* __restrict__ bA, const float* __restrict__ bB,
                 const float* __restrict__ resid, void* __restrict__ outv) {
    extern __shared__ uint8_t smem[];
    uint32_t* patB[2];
    patB[0] = (uint32_t*)smem;
    patB[1] = patB[0] + P_ELEMS;
    uint4* wsmB[2];
    wsmB[0] = (uint4*)(patB[1] + P_ELEMS);
    wsmB[1] = wsmB[0] + WC_U2 / 2;

    const int n = blockIdx.y;
    const int rb = blockIdx.x;
    const int tid = threadIdx.x;
    const int w = tid >> 5;
    const int lane = tid & 31;
    const int qid = lane >> 2;
    const int q = lane & 3;
    const int y0 = rb * 8;

#pragma unroll
    for (int k = 0; k < 23; k++) {
        int i = tid + k * 256;
        if (i < 2 * P_ELEMS) patB[0][i] = 0u;
    }
    __syncthreads();

    float acc[2][8][4];
#pragma unroll
    for (int mt = 0; mt < 2; mt++)
#pragma unroll
        for (int nt = 0; nt < 8; nt++)
#pragma unroll
            for (int r = 0; r < 4; r++) acc[mt][nt][r] = 0.f;

    issue_chunk(patB[0], wsmB[0], (const uint4*)wlayer, inA + n * H2_PER_IMG, y0, tid);
    asm volatile("cp.async.wait_group 0;" ::: "memory");
    __syncthreads();

    const int wtbase = (qid * 4 + q) * 5;

    for (int it = 0; it < 8; ++it) {
        const int p = it & 1;
        if (it < 7) {
            const int jt = it + 1;
            const uint32_t* img = ((jt >= 4) ? inB : inA) + (n * 4 + (jt & 3)) * 8192;
            issue_chunk(patB[1 - p], wsmB[1 - p], (const uint4*)(wlayer + jt * WC_U2),
                        img, y0, tid);
        }
        compute_chunk(patB[p], wsmB[p], w, qid, q, wtbase, acc);
        asm volatile("cp.async.wait_group 0;" ::: "memory");
        __syncthreads();
    }

    const int gy = y0 + w;
    const float cntf = (float)g_cnt[n];
#pragma unroll
    for (int nt = 0; nt < 8; nt++) {
        const int co = nt * 8 + 2 * q;
        const float bias0 = bA[co]     + cntf * bB[co];
        const float bias1 = bA[co + 1] + cntf * bB[co + 1];
#pragma unroll
        for (int mt = 0; mt < 2; mt++) {
            const int xa = mt * 16 + qid;
            const int xc = xa + 8;
            float r0 = acc[mt][nt][0] + bias0;
            float r1 = acc[mt][nt][1] + bias1;
            float r2 = acc[mt][nt][2] + bias0;
            float r3 = acc[mt][nt][3] + bias1;
            if (EPI == 0) {
                float* out = (float*)outv;
                const int o0 = ((n * CCH + co) * HW + gy) * HW;
                r0 += resid[o0 + xa];
                r1 += resid[o0 + 1024 + xa];
                r2 += resid[o0 + xc];
                r3 += resid[o0 + 1024 + xc];
                out[o0 + xa]        = fmaxf(r0, 0.f);
                out[o0 + 1024 + xa] = fmaxf(r1, 0.f);
                out[o0 + xc]        = fmaxf(r2, 0.f);
                out[o0 + 1024 + xc] = fmaxf(r3, 0.f);
            } else {
                uint32_t* out = (uint32_t*)outv;
                const int b0 = ((n * 4 + (co >> 4)) * 8 + ((co >> 1) & 7)) * 1024 + gy * 32;
                out[b0 + xa] = pack_h2(fmaxf(r0, 0.f), fmaxf(r1, 0.f));
                out[b0 + xc] = pack_h2(fmaxf(r2, 0.f), fmaxf(r3, 0.f));
            }
        }
    }
}

// ---------------------------------------------------------------------------
extern "C" void kernel_launch(void* const* d_in, const int* in_sizes, int n_in,
                              void* d_out, int out_size) {
    const float* x    = (const float*)d_in[0];
    const float* w_x0 = (const float*)d_in[1];
    const float* b_x0 = (const float*)d_in[2];
    const float* w_n0 = (const float*)d_in[3];
    const float* b_n0 = (const float*)d_in[4];
    const float* w_x1 = (const float*)d_in[5];
    const float* b_x1 = (const float*)d_in[6];
    const float* w_n1 = (const float*)d_in[7];
    const float* b_n1 = (const float*)d_in[8];
    const void*  msk  = d_in[9];
    float* out = (float*)d_out;

    uint32_t *xh, *xs, *h, *hs;
    uint2* wprep;
    cudaGetSymbolAddress((void**)&xh, g_xh);
    cudaGetSymbolAddress((void**)&xs, g_xs);
    cudaGetSymbolAddress((void**)&h,  g_h);
    cudaGetSymbolAddress((void**)&hs, g_hs);
    cudaGetSymbolAddress((void**)&wprep, g_wprep);

    static bool attr_set = false;
    if (!attr_set) {
        cudaFuncSetAttribute(conv_kernel<0>, cudaFuncAttributeMaxDynamicSharedMemorySize,
                             SMEM_BYTES);
        cudaFuncSetAttribute(conv_kernel<1>, cudaFuncAttributeMaxDynamicSharedMemorySize,
                             SMEM_BYTES);
        attr_set = true;
    }

    dim3 agrid(NODES, 16);
    dim3 cgrid(4, NIMG);

    // launch 0: mask setup
    mask_setup_kernel<<<1, 256>>>(msk);
    // launch 1: weight prep + x->fp16 convert
    prep_cvt_kernel<<<PREP_BLOCKS + CVT_BLOCKS, 256>>>(w_x0, w_n0, w_x1, w_n1,
                                                       x, (uint4*)xh);
    // launch 2: agg1;  launch 3: conv1 (ncu sample slot)
    agg_kernel<<<agrid, 256>>>((const uint4*)xh, (uint4*)xs);
    conv_kernel<1><<<cgrid, 256, SMEM_BYTES>>>(xh, xs, wprep, b_x0, b_n0,
                                               nullptr, (void*)h);
    // launch 4: agg2;  launch 5: conv2
    agg_kernel<<<agrid, 256>>>((const uint4*)h, (uint4*)hs);
    conv_kernel<0><<<cgrid, 256, SMEM_BYTES>>>(h, hs, wprep + 8 * WC_U2, b_x1, b_n1,
                                               x, (void*)out);
}

// round 16
// speedup vs baseline: 1.2941x; 1.1378x over previous
#include <cuda_runtime.h>
#include <cuda_fp16.h>
#include <cstdint>

// Problem constants
#define NIMG 256          // B*L
#define CCH  64
#define HW   32
#define IMGSZ (CCH*HW*HW) // 65536 floats per image
#define NODES 256

// Paired-fp16 tensors: [n][g4][cp8][1024] half2(u32), half2 = (ci=g*16+2cp, +1)
#define H2_PER_IMG 32768
__device__ uint32_t g_xh[NIMG * H2_PER_IMG];   // pairified fp16 x
__device__ uint32_t g_xs[NIMG * H2_PER_IMG];   // aggregated x (fp16)
__device__ uint32_t g_h [NIMG * H2_PER_IMG];   // hidden (fp16)
__device__ uint32_t g_hs[NIMG * H2_PER_IMG];   // aggregated hidden (fp16)
__device__ int g_nbr[NODES * 8];
__device__ int g_cnt[NODES];

// Weights fp16: [layer2][chunk8][tap9][qid8][q4][nt pad10] uint2
#define WC_U2    2880                  // uint2 per chunk: 9*8*4*10
#define W_TAP_U4 160                   // uint4 per tap
#define WPREP_TOTAL (2*8*WC_U2)        // 46080 uint2
__device__ uint2 g_wprep[WPREP_TOTAL];

// patch (half2/u32 elems): [cp8][row10][40], interior at elem 4+gx (16B-aligned)
// P_CSTR=408: mod 32 = 24 -> q*24+qid banks cover 0..31, conflict-free
#define P_CSTR 408
#define P_RSTR 40
#define P_ELEMS 3264                   // 8*408 u32 per buffer
#define SMEM_BYTES (2*P_ELEMS*4 + 2*WC_U2*8)   // 26112 + 46080 = 72192

#define PREP_BLOCKS 180                // 180*256 == WPREP_TOTAL exactly
#define CVT_E4 (NIMG * H2_PER_IMG / 4) // 2097152 uint4 elems
#define CVT_BLOCKS (CVT_E4 / 256)      // 8192

__device__ __forceinline__ uint32_t pack_h2(float a, float b) {
    __half2 h = __floats2half2_rn(a, b);
    return *(uint32_t*)&h;
}
__device__ __forceinline__ float2 h2f(uint32_t u) {
    __half2 h = *(__half2*)&u;
    return __half22float2(h);
}
__device__ __forceinline__ void cp16(void* s, const void* g) {
    uint32_t sa = (uint32_t)__cvta_generic_to_shared(s);
    asm volatile("cp.async.cg.shared.global [%0], [%1], 16;" :: "r"(sa), "l"(g));
}
__device__ __forceinline__ void mma_f16(float& d0, float& d1, float& d2, float& d3,
                                        uint32_t a0, uint32_t a1, uint32_t a2, uint32_t a3,
                                        uint32_t b0, uint32_t b1) {
    asm volatile(
        "mma.sync.aligned.m16n8k16.row.col.f32.f16.f16.f32 "
        "{%0,%1,%2,%3},{%4,%5,%6,%7},{%8,%9},{%0,%1,%2,%3};"
        : "+f"(d0), "+f"(d1), "+f"(d2), "+f"(d3)
        : "r"(a0), "r"(a1), "r"(a2), "r"(a3), "r"(b0), "r"(b1));
}

// ---------------------------------------------------------------------------
// Mask setup: detect dtype then build neighbor lists, one single-block kernel
// ---------------------------------------------------------------------------
__global__ void mask_setup_kernel(const void* m) {
    __shared__ int bad;
    __shared__ int smode;
    int row = threadIdx.x;
    if (row == 0) bad = 0;
    __syncthreads();
    {
        const unsigned char* p = (const unsigned char*)m + row * 64;
        int c = 0;
        for (int j = 0; j < 64; j++) c += (p[j] != 0);
        if (c != 4) atomicOr(&bad, 1);
    }
    __syncthreads();
    int ok8 = !bad;
    __syncthreads();
    if (row == 0) bad = 0;
    __syncthreads();
    if (!ok8) {
        const unsigned short* p = (const unsigned short*)m + row * 64;
        int c = 0;
        for (int j = 0; j < 64; j++) c += (p[j] != 0);
        if (c != 4) atomicOr(&bad, 1);
    }
    __syncthreads();
    if (row == 0) smode = ok8 ? 0 : ((!bad) ? 1 : 2);
    __syncthreads();

    int mode = smode;
    int base = (row >> 6) << 6;
    int cnt = 0;
    if (mode == 0) {
        const unsigned char* p = (const unsigned char*)m + row * 64;
        for (int j = 0; j < 64; j++)
            if (p[j]) { if (cnt < 8) g_nbr[row * 8 + cnt] = base + j; cnt++; }
    } else if (mode == 1) {
        const unsigned short* p = (const unsigned short*)m + row * 64;
        for (int j = 0; j < 64; j++)
            if (p[j]) { if (cnt < 8) g_nbr[row * 8 + cnt] = base + j; cnt++; }
    } else {
        const unsigned int* p = (const unsigned int*)m + row * 64;
        for (int j = 0; j < 64; j++)
            if (p[j]) { if (cnt < 8) g_nbr[row * 8 + cnt] = base + j; cnt++; }
    }
    g_cnt[row] = cnt;
}

// ---------------------------------------------------------------------------
// Fused: weight prep (blocks 0..179) + vectorized x->fp16 convert (rest)
// ---------------------------------------------------------------------------
__global__ void prep_cvt_kernel(const float* __restrict__ w_x0, const float* __restrict__ w_n0,
                                const float* __restrict__ w_x1, const float* __restrict__ w_n1,
                                const float* __restrict__ x, uint4* __restrict__ xh4) {
    if (blockIdx.x < PREP_BLOCKS) {
        int e = blockIdx.x * 256 + threadIdx.x;
        int nt = e % 10; int t = e / 10;
        int q   = t & 3;  t >>= 2;
        int qid = t & 7;  t >>= 3;
        int tap = t % 9;  t /= 9;
        int chunk = t & 7;
        int layer = t >> 3;
        int half = chunk >> 2;
        int cb = (chunk & 3) * 16;
        const float* w = layer ? (half ? w_n1 : w_x1) : (half ? w_n0 : w_x0);
        uint2 v = make_uint2(0u, 0u);
        if (nt < 8) {
            int co = nt * 8 + qid;
            const float* wc = w + co * 576 + tap;
            v.x = pack_h2(wc[(cb + 2 * q) * 9],     wc[(cb + 2 * q + 1) * 9]);
            v.y = pack_h2(wc[(cb + 2 * q + 8) * 9], wc[(cb + 2 * q + 9) * 9]);
        }
        g_wprep[e] = v;
    } else {
        int e4 = (blockIdx.x - PREP_BLOCKS) * 256 + threadIdx.x;
        int p4 = e4 & 255;
        int cp = (e4 >> 8) & 7;
        int g  = (e4 >> 11) & 3;
        int n  = e4 >> 13;
        int ci = g * 16 + cp * 2;
        const float* s = x + (size_t)(n * CCH + ci) * 1024 + p4 * 4;
        float4 lo = *(const float4*)s;
        float4 hi = *(const float4*)(s + 1024);
        xh4[e4] = make_uint4(pack_h2(lo.x, hi.x), pack_h2(lo.y, hi.y),
                             pack_h2(lo.z, hi.z), pack_h2(lo.w, hi.w));
    }
}

// ---------------------------------------------------------------------------
// Neighbor aggregation on fp16 (fp32 accumulate, fp16 out)
// ---------------------------------------------------------------------------
__global__ void agg_kernel(const uint4* __restrict__ src, uint4* __restrict__ dst) {
    int node = blockIdx.x;
    int cnt = g_cnt[node];
    if (cnt > 8) cnt = 8;
    int i0 = blockIdx.y * blockDim.x + threadIdx.x;
    int stride = gridDim.y * blockDim.x;
    int nb[8];
    for (int k = 0; k < cnt; k++) nb[k] = g_nbr[node * 8 + k];
    const int n4 = H2_PER_IMG / 4;
    for (int i = i0; i < n4; i += stride) {
        float2 a0 = make_float2(0.f, 0.f), a1 = a0, a2 = a0, a3 = a0;
        for (int k = 0; k < cnt; k++) {
            uint4 v = src[nb[k] * n4 + i];
            float2 t;
            t = h2f(v.x); a0.x += t.x; a0.y += t.y;
            t = h2f(v.y); a1.x += t.x; a1.y += t.y;
            t = h2f(v.z); a2.x += t.x; a2.y += t.y;
            t = h2f(v.w); a3.x += t.x; a3.y += t.y;
        }
        dst[node * n4 + i] = make_uint4(pack_h2(a0.x, a0.y), pack_h2(a1.x, a1.y),
                                        pack_h2(a2.x, a2.y), pack_h2(a3.x, a3.y));
    }
}

// ---------------------------------------------------------------------------
// Conv: fp16 m16n8k16, R12 tile (warp = 32px x 64co, 256 thr, 2 CTA/SM),
// 8 K16 chunks, 2-stage cp.async pipeline. 16B-aligned patch fill.
// ---------------------------------------------------------------------------
__device__ __forceinline__ void issue_chunk(uint32_t* pat, uint4* wdst,
                                            const uint4* __restrict__ wsrc,
                                            const uint32_t* __restrict__ img,
                                            int y0, int tid) {
#pragma unroll
    for (int k = 0; k < 6; k++) {
        int idx = tid + k * 256;
        if (idx < WC_U2 / 2) cp16(wdst + idx, wsrc + idx);
    }
    // patch: 640 cp16 ops (8 cp x 10 rows x 8 col-quads of half2), 16B-aligned
#pragma unroll
    for (int k = 0; k < 3; k++) {
        int i = tid + k * 256;
        if (i < 640) {
            int col = (i & 7) * 4;
            int r = (i >> 3) % 10;
            int cp = i / 80;
            int gy = y0 + r - 1;
            if (gy >= 0 && gy < HW)
                cp16(pat + cp * P_CSTR + r * P_RSTR + 4 + col,
                     img + cp * 1024 + gy * 32 + col);
        }
    }
    asm volatile("cp.async.commit_group;" ::: "memory");
}

__device__ __forceinline__ void compute_chunk(const uint32_t* __restrict__ pat,
                                              const uint4* __restrict__ wq,
                                              int w, int qid, int q, int wtbase,
                                              float (&acc)[2][8][4]) {
    uint4 bb[2][4];
#pragma unroll
    for (int j = 0; j < 4; j++) bb[0][j] = wq[wtbase + j];

#pragma unroll
    for (int tap = 0; tap < 9; tap++) {
        const int ty = tap / 3, tx = tap % 3;
        const int cur = tap & 1;
        if (tap < 8) {
            const uint4* wn = wq + (tap + 1) * W_TAP_U4 + wtbase;
#pragma unroll
            for (int j = 0; j < 4; j++) bb[1 - cur][j] = wn[j];
        }
        // interior at elem 4: gx = qid+tx-1  ->  elem 4+gx = qid+tx+3
        const int ro = (w + ty) * P_RSTR + qid + tx + 3;
        const int blo = q * P_CSTR + ro;
        const int bhi = (q + 4) * P_CSTR + ro;
        uint32_t a[2][4];
#pragma unroll
        for (int mt = 0; mt < 2; mt++) {
            const int xo = mt * 16;
            a[mt][0] = pat[blo + xo];
            a[mt][1] = pat[blo + xo + 8];
            a[mt][2] = pat[bhi + xo];
            a[mt][3] = pat[bhi + xo + 8];
        }
        const uint32_t* b = (const uint32_t*)bb[cur];
#pragma unroll
        for (int mt = 0; mt < 2; mt++)
#pragma unroll
            for (int nt = 0; nt < 8; nt++)
                mma_f16(acc[mt][nt][0], acc[mt][nt][1],
                        acc[mt][nt][2], acc[mt][nt][3],
                        a[mt][0], a[mt][1], a[mt][2], a[mt][3],
                        b[2 * nt], b[2 * nt + 1]);
    }
}

// EPI 0: fp32 out + residual; EPI 1: paired-fp16 out (h)
template <int EPI>
__global__ __launch_bounds__(256, 2)
void conv_kernel(const uint32_t* __restrict__ inA, const uint32_t* __restrict__ inB,
                 const uint2* __restrict__ wlayer,
                 const float* __restrict__ bA, const float* __restrict__ bB,
                 const float* __restrict__ resid, void* __restrict__ outv) {
    extern __shared__ uint8_t smem[];
    uint32_t* patB[2];
    patB[0] = (uint32_t*)smem;
    patB[1] = patB[0] + P_ELEMS;
    uint4* wsmB[2];
    wsmB[0] = (uint4*)(patB[1] + P_ELEMS);
    wsmB[1] = wsmB[0] + WC_U2 / 2;

    const int n = blockIdx.y;
    const int rb = blockIdx.x;
    const int tid = threadIdx.x;
    const int w = tid >> 5;
    const int lane = tid & 31;
    const int qid = lane >> 2;
    const int q = lane & 3;
    const int y0 = rb * 8;

    // zero both patch buffers once (halo cells stay zero)
#pragma unroll
    for (int k = 0; k < 26; k++) {
        int i = tid + k * 256;
        if (i < 2 * P_ELEMS) patB[0][i] = 0u;
    }
    __syncthreads();

    float acc[2][8][4];
#pragma unroll
    for (int mt = 0; mt < 2; mt++)
#pragma unroll
        for (int nt = 0; nt < 8; nt++)
#pragma unroll
            for (int r = 0; r < 4; r++) acc[mt][nt][r] = 0.f;

    issue_chunk(patB[0], wsmB[0], (const uint4*)wlayer, inA + n * H2_PER_IMG, y0, tid);
    asm volatile("cp.async.wait_group 0;" ::: "memory");
    __syncthreads();

    const int wtbase = (qid * 4 + q) * 5;

    for (int it = 0; it < 8; ++it) {
        const int p = it & 1;
        if (it < 7) {
            const int jt = it + 1;
            const uint32_t* img = ((jt >= 4) ? inB : inA) + (n * 4 + (jt & 3)) * 8192;
            issue_chunk(patB[1 - p], wsmB[1 - p], (const uint4*)(wlayer + jt * WC_U2),
                        img, y0, tid);
        }
        compute_chunk(patB[p], wsmB[p], w, qid, q, wtbase, acc);
        if (it < 7) {
            asm volatile("cp.async.wait_group 0;" ::: "memory");
            __syncthreads();
        }
    }

    const int gy = y0 + w;
    const float cntf = (float)g_cnt[n];
#pragma unroll
    for (int nt = 0; nt < 8; nt++) {
        const int co = nt * 8 + 2 * q;
        const float bias0 = bA[co]     + cntf * bB[co];
        const float bias1 = bA[co + 1] + cntf * bB[co + 1];
#pragma unroll
        for (int mt = 0; mt < 2; mt++) {
            const int xa = mt * 16 + qid;
            const int xc = xa + 8;
            float r0 = acc[mt][nt][0] + bias0;
            float r1 = acc[mt][nt][1] + bias1;
            float r2 = acc[mt][nt][2] + bias0;
            float r3 = acc[mt][nt][3] + bias1;
            if (EPI == 0) {
                float* out = (float*)outv;
                const int o0 = ((n * CCH + co) * HW + gy) * HW;
                r0 += resid[o0 + xa];
                r1 += resid[o0 + 1024 + xa];
                r2 += resid[o0 + xc];
                r3 += resid[o0 + 1024 + xc];
                out[o0 + xa]        = fmaxf(r0, 0.f);
                out[o0 + 1024 + xa] = fmaxf(r1, 0.f);
                out[o0 + xc]        = fmaxf(r2, 0.f);
                out[o0 + 1024 + xc] = fmaxf(r3, 0.f);
            } else {
                uint32_t* out = (uint32_t*)outv;
                const int b0 = ((n * 4 + (co >> 4)) * 8 + ((co >> 1) & 7)) * 1024 + gy * 32;
                out[b0 + xa] = pack_h2(fmaxf(r0, 0.f), fmaxf(r1, 0.f));
                out[b0 + xc] = pack_h2(fmaxf(r2, 0.f), fmaxf(r3, 0.f));
            }
        }
    }
}

// ---------------------------------------------------------------------------
extern "C" void kernel_launch(void* const* d_in, const int* in_sizes, int n_in,
                              void* d_out, int out_size) {
    const float* x    = (const float*)d_in[0];
    const float* w_x0 = (const float*)d_in[1];
    const float* b_x0 = (const float*)d_in[2];
    const float* w_n0 = (const float*)d_in[3];
    const float* b_n0 = (const float*)d_in[4];
    const float* w_x1 = (const float*)d_in[5];
    const float* b_x1 = (const float*)d_in[6];
    const float* w_n1 = (const float*)d_in[7];
    const float* b_n1 = (const float*)d_in[8];
    const void*  msk  = d_in[9];
    float* out = (float*)d_out;

    uint32_t *xh, *xs, *h, *hs;
    uint2* wprep;
    cudaGetSymbolAddress((void**)&xh, g_xh);
    cudaGetSymbolAddress((void**)&xs, g_xs);
    cudaGetSymbolAddress((void**)&h,  g_h);
    cudaGetSymbolAddress((void**)&hs, g_hs);
    cudaGetSymbolAddress((void**)&wprep, g_wprep);

    static bool attr_set = false;
    if (!attr_set) {
        cudaFuncSetAttribute(conv_kernel<0>, cudaFuncAttributeMaxDynamicSharedMemorySize,
                             SMEM_BYTES);
        cudaFuncSetAttribute(conv_kernel<1>, cudaFuncAttributeMaxDynamicSharedMemorySize,
                             SMEM_BYTES);
        attr_set = true;
    }

    dim3 agrid(NODES, 16);
    dim3 cgrid(4, NIMG);

    // launch 0: mask setup
    mask_setup_kernel<<<1, 256>>>(msk);
    // launch 1: weight prep + x->fp16 convert
    prep_cvt_kernel<<<PREP_BLOCKS + CVT_BLOCKS, 256>>>(w_x0, w_n0, w_x1, w_n1,
                                                       x, (uint4*)xh);
    // launch 2: agg1;  launch 3: conv1 (ncu sample slot)
    agg_kernel<<<agrid, 256>>>((const uint4*)xh, (uint4*)xs);
    conv_kernel<1><<<cgrid, 256, SMEM_BYTES>>>(xh, xs, wprep, b_x0, b_n0,
                                               nullptr, (void*)h);
    // launch 4: agg2;  launch 5: conv2
    agg_kernel<<<agrid, 256>>>((const uint4*)h, (uint4*)hs);
    conv_kernel<0><<<cgrid, 256, SMEM_BYTES>>>(h, hs, wprep + 8 * WC_U2, b_x1, b_n1,
                                               x, (void*)out);
}